// round 1
// baseline (speedup 1.0000x reference)
#include <cuda_runtime.h>

#define NB     256
#define NPIX   (1024*1024)
#define NBATCH 16

// Scratch (no allocations allowed) — re-zeroed every launch by zero_kernel.
__device__ int   g_histo[NBATCH][NB];
__device__ float g_lut[NBATCH][NB];
__device__ float g_step[NBATCH];

__device__ __forceinline__ float clip01(float x) {
    return fminf(fmaxf(x, 0.0f), 1.0f);
}

__global__ void zero_kernel() {
    int i = blockIdx.x * blockDim.x + threadIdx.x;
    if (i < NBATCH * NB) ((int*)g_histo)[i] = 0;
}

// Pass 1: per-image histogram of Y bins.
__global__ void hist_kernel(const float* __restrict__ img) {
    __shared__ int sh[NB];
    for (int i = threadIdx.x; i < NB; i += blockDim.x) sh[i] = 0;
    __syncthreads();

    const int b = blockIdx.y;
    const float4* __restrict__ R = (const float4*)(img + (size_t)b * 3 * NPIX);
    const float4* __restrict__ G = (const float4*)(img + (size_t)b * 3 * NPIX + NPIX);
    const float4* __restrict__ B = (const float4*)(img + (size_t)b * 3 * NPIX + 2 * NPIX);

    const int   n4     = NPIX / 4;
    const int   stride = gridDim.x * blockDim.x;
    const float scale  = (float)(256.0 / 255.0);   // NUM_BINS / 255.0 cast to f32

    for (int i = blockIdx.x * blockDim.x + threadIdx.x; i < n4; i += stride) {
        float4 r4 = R[i], g4 = G[i], b4 = B[i];
        #pragma unroll
        for (int c = 0; c < 4; c++) {
            float r = clip01(((const float*)&r4)[c]);
            float g = clip01(((const float*)&g4)[c]);
            float bb = clip01(((const float*)&b4)[c]);
            float y = 0.299f * r + 0.587f * g + 0.114f * bb;
            float t = y * 255.0f;
            int bin = (int)floorf(t * scale);
            bin = min(max(bin, 0), NB - 1);
            atomicAdd(&sh[bin], 1);
        }
    }
    __syncthreads();
    for (int i = threadIdx.x; i < NB; i += blockDim.x)
        if (sh[i]) atomicAdd(&g_histo[b][i], sh[i]);
}

// LUT: one block per image, 256 threads (one per bin).
__global__ void lut_kernel() {
    const int b = blockIdx.x;
    const int t = threadIdx.x;

    __shared__ float h[NB];
    __shared__ float s[NB];
    __shared__ int   lastIdx;

    float hv = (float)g_histo[b][t];
    h[t] = hv;
    s[t] = hv;
    if (t == 0) lastIdx = 0;
    __syncthreads();

    // Inclusive Hillis-Steele scan (fp32 exact: counts < 2^24).
    for (int off = 1; off < NB; off <<= 1) {
        float add = (t >= off) ? s[t - off] : 0.0f;
        __syncthreads();
        s[t] += add;
        __syncthreads();
    }

    if (hv > 0.0f) atomicMax(&lastIdx, t);
    __syncthreads();

    float total    = s[NB - 1];          // == sum(histo), exact in fp32
    float last_val = h[lastIdx];
    float step     = floorf(__fdiv_rn(total - last_val, 255.0f));
    float safe     = fmaxf(step, 1.0f);
    float half     = floorf(__fdiv_rn(step, 2.0f));

    float lv;
    if (t == 0) {
        lv = 0.0f;                        // lut[0] forced to zero
    } else {
        lv = floorf(__fdiv_rn(s[t - 1] + half, safe));   // exclusive cumsum at t
        lv = fminf(fmaxf(lv, 0.0f), 255.0f);
    }
    g_lut[b][t] = lv;
    if (t == 0) g_step[b] = step;
}

// Pass 2: map Y through LUT, recombine with U/V, convert back to RGB.
__global__ void map_kernel(const float* __restrict__ img, float* __restrict__ out) {
    __shared__ float lut[NB];
    __shared__ float stepv;

    const int b = blockIdx.y;
    for (int i = threadIdx.x; i < NB; i += blockDim.x) lut[i] = g_lut[b][i];
    if (threadIdx.x == 0) stepv = g_step[b];
    __syncthreads();

    const bool identity = (stepv == 0.0f);

    const float4* __restrict__ R = (const float4*)(img + (size_t)b * 3 * NPIX);
    const float4* __restrict__ G = (const float4*)(img + (size_t)b * 3 * NPIX + NPIX);
    const float4* __restrict__ B = (const float4*)(img + (size_t)b * 3 * NPIX + 2 * NPIX);
    float4* __restrict__ Ro = (float4*)(out + (size_t)b * 3 * NPIX);
    float4* __restrict__ Go = (float4*)(out + (size_t)b * 3 * NPIX + NPIX);
    float4* __restrict__ Bo = (float4*)(out + (size_t)b * 3 * NPIX + 2 * NPIX);

    const int n4     = NPIX / 4;
    const int stride = gridDim.x * blockDim.x;

    for (int i = blockIdx.x * blockDim.x + threadIdx.x; i < n4; i += stride) {
        float4 r4 = R[i], g4 = G[i], b4 = B[i];
        float4 ro, go, bo;
        #pragma unroll
        for (int c = 0; c < 4; c++) {
            float r  = clip01(((const float*)&r4)[c]);
            float g  = clip01(((const float*)&g4)[c]);
            float bb = clip01(((const float*)&b4)[c]);

            float y = 0.299f * r + 0.587f * g + 0.114f * bb;
            float u = -0.147f * r - 0.289f * g + 0.436f * bb;
            float v = 0.615f * r - 0.515f * g - 0.100f * bb;

            float t = y * 255.0f;
            int gi = min(max((int)t, 0), NB - 1);
            float outv = identity ? t : lut[gi];
            float ye = __fdiv_rn(outv, 255.0f);

            ((float*)&ro)[c] = ye + 1.14f * v;
            ((float*)&go)[c] = ye - 0.396f * u - 0.581f * v;
            ((float*)&bo)[c] = ye + 2.029f * u;
        }
        Ro[i] = ro;
        Go[i] = go;
        Bo[i] = bo;
    }
}

extern "C" void kernel_launch(void* const* d_in, const int* in_sizes, int n_in,
                              void* d_out, int out_size) {
    const float* img = (const float*)d_in[0];
    float*       out = (float*)d_out;

    zero_kernel<<<16, 256>>>();
    dim3 hg(256, NBATCH);
    hist_kernel<<<hg, 256>>>(img);
    lut_kernel<<<NBATCH, 256>>>();
    dim3 mg(256, NBATCH);
    map_kernel<<<mg, 256>>>(img, out);
}

// round 2
// speedup vs baseline: 1.0162x; 1.0162x over previous
#include <cuda_runtime.h>

#define NB     256
#define NPIX   (1024*1024)
#define NBATCH 16
#define G      4                 // images per group (50 MB input, fits L2 with headroom)
#define NGROUP (NBATCH / G)
#define IT     4                 // float4 items per thread
#define TPB    256
#define BLKX   (NPIX / 4 / (TPB * IT))   // 256 blocks per image

// Scratch (no allocations allowed). g_histo is zero at module load and re-zeroed
// by lut_kernel after consumption, so every graph replay sees zeros.
__device__ int   g_histo[NBATCH][NB];
__device__ float g_lut[NBATCH][NB];
__device__ float g_step[NBATCH];

__device__ __forceinline__ float clip01(float x) {
    return fminf(fmaxf(x, 0.0f), 1.0f);
}

// Pass 1: per-image histogram of Y bins. Normal (evict-normal) loads so the
// group's input stays resident in L2 for map_kernel.
__global__ void hist_kernel(const float* __restrict__ img, int img_base) {
    __shared__ int sh[NB];
    for (int i = threadIdx.x; i < NB; i += blockDim.x) sh[i] = 0;
    __syncthreads();

    const int b = img_base + blockIdx.y;
    const size_t base = (size_t)b * 3 * NPIX;
    const float4* __restrict__ R = (const float4*)(img + base);
    const float4* __restrict__ Gc = (const float4*)(img + base + NPIX);
    const float4* __restrict__ B = (const float4*)(img + base + 2 * NPIX);

    const int tile = blockIdx.x * (TPB * IT);
    const float scale = (float)(256.0 / 255.0);   // NUM_BINS / 255.0 in f32

    #pragma unroll
    for (int k = 0; k < IT; k++) {
        int i = tile + k * TPB + threadIdx.x;
        float4 r4 = R[i], g4 = Gc[i], b4 = B[i];
        #pragma unroll
        for (int c = 0; c < 4; c++) {
            float r  = clip01(((const float*)&r4)[c]);
            float g  = clip01(((const float*)&g4)[c]);
            float bb = clip01(((const float*)&b4)[c]);
            float y = 0.299f * r + 0.587f * g + 0.114f * bb;
            int bin = (int)floorf(y * 255.0f * scale);
            bin = min(max(bin, 0), NB - 1);
            atomicAdd(&sh[bin], 1);
        }
    }
    __syncthreads();
    for (int i = threadIdx.x; i < NB; i += blockDim.x)
        if (sh[i]) atomicAdd(&g_histo[b][i], sh[i]);
}

// LUT: one block per image in the group; also resets the histogram for the
// next graph replay.
__global__ void lut_kernel(int img_base) {
    const int b = img_base + blockIdx.x;
    const int t = threadIdx.x;

    __shared__ float h[NB];
    __shared__ float s[NB];
    __shared__ int   lastIdx;

    float hv = (float)g_histo[b][t];
    g_histo[b][t] = 0;                    // reset for next replay
    h[t] = hv;
    s[t] = hv;
    if (t == 0) lastIdx = 0;
    __syncthreads();

    // Inclusive Hillis-Steele scan (fp32 exact: counts < 2^24).
    for (int off = 1; off < NB; off <<= 1) {
        float add = (t >= off) ? s[t - off] : 0.0f;
        __syncthreads();
        s[t] += add;
        __syncthreads();
    }

    if (hv > 0.0f) atomicMax(&lastIdx, t);
    __syncthreads();

    float total    = s[NB - 1];
    float last_val = h[lastIdx];
    float step     = floorf(__fdiv_rn(total - last_val, 255.0f));
    float safe     = fmaxf(step, 1.0f);
    float half     = floorf(__fdiv_rn(step, 2.0f));

    float lv;
    if (t == 0) {
        lv = 0.0f;
    } else {
        lv = floorf(__fdiv_rn(s[t - 1] + half, safe));
        lv = fminf(fmaxf(lv, 0.0f), 255.0f);
    }
    g_lut[b][t] = lv;
    if (t == 0) g_step[b] = step;
}

// Pass 2: map Y through LUT, recombine with U/V, convert back to RGB.
// __ldcs: input is last-touch (staged by hist, evict after read).
// __stcs: output is never re-read — streaming store keeps L2 for staging.
__global__ void map_kernel(const float* __restrict__ img, float* __restrict__ out,
                           int img_base) {
    __shared__ float lut[NB];
    __shared__ float stepv;

    const int b = img_base + blockIdx.y;
    for (int i = threadIdx.x; i < NB; i += blockDim.x) lut[i] = g_lut[b][i];
    if (threadIdx.x == 0) stepv = g_step[b];
    __syncthreads();

    const bool identity = (stepv == 0.0f);

    const size_t base = (size_t)b * 3 * NPIX;
    const float4* __restrict__ R = (const float4*)(img + base);
    const float4* __restrict__ Gc = (const float4*)(img + base + NPIX);
    const float4* __restrict__ B = (const float4*)(img + base + 2 * NPIX);
    float4* __restrict__ Ro = (float4*)(out + base);
    float4* __restrict__ Go = (float4*)(out + base + NPIX);
    float4* __restrict__ Bo = (float4*)(out + base + 2 * NPIX);

    const int tile = blockIdx.x * (TPB * IT);

    #pragma unroll
    for (int k = 0; k < IT; k++) {
        int i = tile + k * TPB + threadIdx.x;
        float4 r4 = __ldcs(R + i);
        float4 g4 = __ldcs(Gc + i);
        float4 b4 = __ldcs(B + i);
        float4 ro, go, bo;
        #pragma unroll
        for (int c = 0; c < 4; c++) {
            float r  = clip01(((const float*)&r4)[c]);
            float g  = clip01(((const float*)&g4)[c]);
            float bb = clip01(((const float*)&b4)[c]);

            float y = 0.299f * r + 0.587f * g + 0.114f * bb;
            float u = -0.147f * r - 0.289f * g + 0.436f * bb;
            float v = 0.615f * r - 0.515f * g - 0.100f * bb;

            float t = y * 255.0f;
            int gi = min(max((int)t, 0), NB - 1);
            float outv = identity ? t : lut[gi];
            float ye = __fdiv_rn(outv, 255.0f);

            ((float*)&ro)[c] = ye + 1.14f * v;
            ((float*)&go)[c] = ye - 0.396f * u - 0.581f * v;
            ((float*)&bo)[c] = ye + 2.029f * u;
        }
        __stcs(Ro + i, ro);
        __stcs(Go + i, go);
        __stcs(Bo + i, bo);
    }
}

// Lazy one-time resources (created on the correctness call, outside capture).
static bool         g_inited = false;
static cudaStream_t g_s1;
static cudaEvent_t  g_evLut[NGROUP];
static cudaEvent_t  g_evDone;

extern "C" void kernel_launch(void* const* d_in, const int* in_sizes, int n_in,
                              void* d_out, int out_size) {
    const float* img = (const float*)d_in[0];
    float*       out = (float*)d_out;

    if (!g_inited) {
        cudaStreamCreateWithFlags(&g_s1, cudaStreamNonBlocking);
        for (int g = 0; g < NGROUP; g++)
            cudaEventCreateWithFlags(&g_evLut[g], cudaEventDisableTiming);
        cudaEventCreateWithFlags(&g_evDone, cudaEventDisableTiming);
        g_inited = true;
    }

    // Pipeline: hist(g)+lut(g) on the origin stream; map(g) on g_s1 gated by
    // lut(g). hist(g+1) then overlaps map(g). Joined at the end so capture
    // sees a single connected graph.
    for (int g = 0; g < NGROUP; g++) {
        dim3 grid(BLKX, G);
        hist_kernel<<<grid, TPB>>>(img, g * G);
        lut_kernel<<<G, NB>>>(g * G);
        cudaEventRecord(g_evLut[g], 0);
        cudaStreamWaitEvent(g_s1, g_evLut[g], 0);
        map_kernel<<<grid, TPB, 0, g_s1>>>(img, out, g * G);
    }
    cudaEventRecord(g_evDone, g_s1);
    cudaStreamWaitEvent(0, g_evDone, 0);
}